// round 17
// baseline (speedup 1.0000x reference)
#include <cuda_runtime.h>
#include <cuda_bf16.h>

// 3-layer LSTM, B=1024, T=1024, H=20, IN=1, OUT=2, FC on last h2.
// R17 = R16 + C-row split across batches: lanes 0-15 compute gate rows 64-79
// for gb0, lanes 16-31 for gb1 (same weight regs) -> each 20-k chunk does
// 5 row-MACs instead of 6 (-17% FFMA2). Biases folded into accumulator init.

#define T_LEN 1024
#define HID   20
#define FULLM 0xffffffffu
#define NW    6
#define GB    2

typedef unsigned long long u64;

__device__ __forceinline__ void ffma2(u64 &acc, u64 a, u64 b) {
    asm("fma.rn.f32x2 %0, %1, %2, %0;" : "+l"(acc) : "l"(a), "l"(b));
}
__device__ __forceinline__ u64 pack2f(float lo, float hi) {
    u64 r; asm("mov.b64 %0, {%1, %2};" : "=l"(r) : "f"(lo), "f"(hi)); return r;
}
__device__ __forceinline__ float hadd(u64 v) {
    float lo, hi;
    asm("mov.b64 {%0, %1}, %2;" : "=f"(lo), "=f"(hi) : "l"(v));
    return lo + hi;
}

// ---- MUFU.TANH-based activations ----
__device__ __forceinline__ float tanhap(float x) {
    float y;
    asm("tanh.approx.f32 %0, %1;" : "=f"(y) : "f"(x));
    return y;
}
__device__ __forceinline__ float fsig(float x) {
    return fmaf(0.5f, tanhap(0.5f * x), 0.5f);
}
__device__ __forceinline__ float cellup(float pi, float pf, float pg, float po,
                                        float &c) {
    c = fsig(pf) * c + fsig(pi) * tanhap(pg);
    return fsig(po) * tanhap(c);
}

// 5-row MAC over one 20-k chunk (10 k-pairs) at weight offset `off`:
// rows A,B for both batches + row C for this lane's own batch (hC).
__device__ __forceinline__ void mac5(u64 &aA0, u64 &aB0, u64 &aA1, u64 &aB1,
                                     u64 &aC,
                                     const ulonglong2* __restrict__ h0,
                                     const ulonglong2* __restrict__ h1,
                                     const ulonglong2* __restrict__ hC,
                                     const u64* __restrict__ WA,
                                     const u64* __restrict__ WB,
                                     const u64* __restrict__ WC, int off)
{
#pragma unroll
    for (int i = 0; i < 5; i++) {
        ulonglong2 v0 = h0[i], v1 = h1[i], vc = hC[i];
        ffma2(aA0, v0.x, WA[off + 2*i]); ffma2(aA0, v0.y, WA[off + 2*i + 1]);
        ffma2(aB0, v0.x, WB[off + 2*i]); ffma2(aB0, v0.y, WB[off + 2*i + 1]);
        ffma2(aA1, v1.x, WA[off + 2*i]); ffma2(aA1, v1.y, WA[off + 2*i + 1]);
        ffma2(aB1, v1.x, WB[off + 2*i]); ffma2(aB1, v1.y, WB[off + 2*i + 1]);
        ffma2(aC,  vc.x, WC[off + 2*i]); ffma2(aC,  vc.y, WC[off + 2*i + 1]);
    }
}

__global__ void __launch_bounds__(NW * 32, 2)
lstm3_rows(const float* __restrict__ x,
           const float* __restrict__ wih0, const float* __restrict__ whh0,
           const float* __restrict__ bih0, const float* __restrict__ bhh0,
           const float* __restrict__ wih1, const float* __restrict__ whh1,
           const float* __restrict__ bih1, const float* __restrict__ bhh1,
           const float* __restrict__ wih2, const float* __restrict__ whh2,
           const float* __restrict__ bih2, const float* __restrict__ bhh2,
           const float* __restrict__ fcw,  const float* __restrict__ fcb,
           float* __restrict__ out)
{
    // h buffers: [layer][pipe][slot = t&3][gb][20 floats]
    __shared__ __align__(16) float4 s_h[3][2][4][GB][5];
    // per-warp, per-gb row-sum scratch, unit-major: ps[gb][u*4+g]
    __shared__ __align__(16) float s_ps[NW][GB][80];

    const int tid  = threadIdx.x;
    const int lane = tid & 31;
    const int wid  = tid >> 5;

    {   // zero all 4 slots of all h buffers
        float4* p = &s_h[0][0][0][0][0];
        for (int i = tid; i < 3 * 2 * 4 * GB * 5; i += NW * 32)
            p[i] = make_float4(0.f, 0.f, 0.f, 0.f);
    }
    __syncthreads();

    // role map: S0={L1p0,L0p0} S1={L2p0,L0p1} S2={L1p1} S3={L2p1}
    int role, pipe;
    if (wid < 4) { role = 1 + (wid & 1); pipe = wid >> 1; }
    else         { role = 0;             pipe = wid - 4;  }
    const int barid = 1 + pipe;

    const int bbase = blockIdx.x * (2 * GB) + pipe * GB;

    // gate-row assignment (rows: i 0-19, f 20-39, g 40-59, o 60-79)
    const int rA  = lane;               // rows 0..31
    const int rB  = lane + 32;          // rows 32..63
    const int rC  = 64 + (lane & 15);   // rows 64..79; lane<16 -> gb0, >=16 -> gb1
    const int cgb = lane >> 4;          // which batch this lane's C row serves
    const int jc  = (lane < HID) ? lane : (HID - 1);

    const int adA = (rA % 20) * 4 + rA / 20;
    const int adB = (rB % 20) * 4 + rB / 20;
    const int adC = (rC % 20) * 4 + rC / 20;

    // ---- per-lane register weights + row biases ----
    u64 WA[20], WB[20], WC[20];
    u64 bA64, bB64, bC64;
    float4 wx4 = make_float4(0.f, 0.f, 0.f, 0.f);
    {
        const float* wi = (role == 0) ? wih0 : ((role == 1) ? wih1 : wih2);
        const float* wh = (role == 0) ? whh0 : ((role == 1) ? whh1 : whh2);
        const float* bi = (role == 0) ? bih0 : ((role == 1) ? bih1 : bih2);
        const float* bh = (role == 0) ? bhh0 : ((role == 1) ? bhh1 : bhh2);
        if (role == 0) {
#pragma unroll
            for (int m = 0; m < 10; m++) {
                WA[m] = *(const u64*)(wh + rA * HID + 2 * m);
                WB[m] = *(const u64*)(wh + rB * HID + 2 * m);
                WC[m] = *(const u64*)(wh + rC * HID + 2 * m);
            }
            wx4 = make_float4(wi[jc], wi[20 + jc], wi[40 + jc], wi[60 + jc]);
        } else {
#pragma unroll
            for (int m = 0; m < 10; m++) {
                WA[m]      = *(const u64*)(wi + rA * HID + 2 * m);
                WA[10 + m] = *(const u64*)(wh + rA * HID + 2 * m);
                WB[m]      = *(const u64*)(wi + rB * HID + 2 * m);
                WB[10 + m] = *(const u64*)(wh + rB * HID + 2 * m);
                WC[m]      = *(const u64*)(wi + rC * HID + 2 * m);
                WC[10 + m] = *(const u64*)(wh + rC * HID + 2 * m);
            }
        }
        bA64 = pack2f(bi[rA] + bh[rA], 0.f);
        bB64 = pack2f(bi[rB] + bh[rB], 0.f);
        bC64 = pack2f(bi[rC] + bh[rC], 0.f);
    }

    float cst[GB] = {0.f, 0.f};
    float xs[GB]  = {0.f, 0.f};

    // interval m: L0 does t=2m,2m+1; L1 t=2m-2,2m-1; L2 t=2m-4,2m-3
    for (int m = 0; m <= 513; m++) {
        if (role == 0) {
            if (m <= 511) {
#pragma unroll
                for (int s = 0; s < 2; s++) {
                    const int t = 2 * m + s;
                    if ((t & 31) == 0) {
#pragma unroll
                        for (int gb = 0; gb < GB; gb++)
                            xs[gb] = x[(long)(bbase + gb) * T_LEN + t + lane];
                    }
                    const int pw = t & 3, pr = (t - 1) & 3;
                    float xv0 = __shfl_sync(FULLM, xs[0], t & 31);
                    float xv1 = __shfl_sync(FULLM, xs[1], t & 31);
                    const ulonglong2* r0 =
                        (const ulonglong2*)&s_h[0][pipe][pr][0][0];
                    const ulonglong2* r1 =
                        (const ulonglong2*)&s_h[0][pipe][pr][1][0];
                    u64 aA0 = bA64, aB0 = bB64, aA1 = bA64, aB1 = bB64;
                    u64 aC  = bC64;
                    mac5(aA0, aB0, aA1, aB1, aC, r0, r1, cgb ? r1 : r0,
                         WA, WB, WC, 0);
                    s_ps[wid][0][adA] = hadd(aA0);
                    s_ps[wid][0][adB] = hadd(aB0);
                    s_ps[wid][1][adA] = hadd(aA1);
                    s_ps[wid][1][adB] = hadd(aB1);
                    s_ps[wid][cgb][adC] = hadd(aC);
                    __syncwarp();
                    float4 G0 = *(const float4*)&s_ps[wid][0][jc * 4];
                    float4 G1 = *(const float4*)&s_ps[wid][1][jc * 4];
                    float h0 = cellup(fmaf(xv0, wx4.x, G0.x),
                                      fmaf(xv0, wx4.y, G0.y),
                                      fmaf(xv0, wx4.z, G0.z),
                                      fmaf(xv0, wx4.w, G0.w), cst[0]);
                    float h1 = cellup(fmaf(xv1, wx4.x, G1.x),
                                      fmaf(xv1, wx4.y, G1.y),
                                      fmaf(xv1, wx4.z, G1.z),
                                      fmaf(xv1, wx4.w, G1.w), cst[1]);
                    if (lane < HID) {
                        ((float*)&s_h[0][pipe][pw][0][0])[lane] = h0;
                        ((float*)&s_h[0][pipe][pw][1][0])[lane] = h1;
                    }
                    __syncwarp();
                }
            }
        } else if (role == 1) {
            if (m >= 1 && m <= 512) {
#pragma unroll
                for (int s = 0; s < 2; s++) {
                    const int t = 2 * m - 2 + s;
                    const int pw = t & 3, pr = (t - 1) & 3;
                    const ulonglong2* p0 =
                        (const ulonglong2*)&s_h[0][pipe][pw][0][0];  // h0[t]
                    const ulonglong2* p1 =
                        (const ulonglong2*)&s_h[0][pipe][pw][1][0];
                    const ulonglong2* q0 =
                        (const ulonglong2*)&s_h[1][pipe][pr][0][0];  // h1[t-1]
                    const ulonglong2* q1 =
                        (const ulonglong2*)&s_h[1][pipe][pr][1][0];
                    u64 aA0 = bA64, aB0 = bB64, aA1 = bA64, aB1 = bB64;
                    u64 aC  = bC64;
                    mac5(aA0, aB0, aA1, aB1, aC, p0, p1, cgb ? p1 : p0,
                         WA, WB, WC, 0);
                    mac5(aA0, aB0, aA1, aB1, aC, q0, q1, cgb ? q1 : q0,
                         WA, WB, WC, 10);
                    s_ps[wid][0][adA] = hadd(aA0);
                    s_ps[wid][0][adB] = hadd(aB0);
                    s_ps[wid][1][adA] = hadd(aA1);
                    s_ps[wid][1][adB] = hadd(aB1);
                    s_ps[wid][cgb][adC] = hadd(aC);
                    __syncwarp();
                    float4 G0 = *(const float4*)&s_ps[wid][0][jc * 4];
                    float4 G1 = *(const float4*)&s_ps[wid][1][jc * 4];
                    float h0 = cellup(G0.x, G0.y, G0.z, G0.w, cst[0]);
                    float h1 = cellup(G1.x, G1.y, G1.z, G1.w, cst[1]);
                    if (lane < HID) {
                        ((float*)&s_h[1][pipe][pw][0][0])[lane] = h0;
                        ((float*)&s_h[1][pipe][pw][1][0])[lane] = h1;
                    }
                    __syncwarp();
                }
            }
        } else {
            if (m >= 2) {
#pragma unroll
                for (int s = 0; s < 2; s++) {
                    const int t = 2 * m - 4 + s;
                    const int pw = t & 3, pr = (t - 1) & 3;
                    const ulonglong2* p0 =
                        (const ulonglong2*)&s_h[1][pipe][pw][0][0];  // h1[t]
                    const ulonglong2* p1 =
                        (const ulonglong2*)&s_h[1][pipe][pw][1][0];
                    const ulonglong2* q0 =
                        (const ulonglong2*)&s_h[2][pipe][pr][0][0];  // h2[t-1]
                    const ulonglong2* q1 =
                        (const ulonglong2*)&s_h[2][pipe][pr][1][0];
                    u64 aA0 = bA64, aB0 = bB64, aA1 = bA64, aB1 = bB64;
                    u64 aC  = bC64;
                    mac5(aA0, aB0, aA1, aB1, aC, p0, p1, cgb ? p1 : p0,
                         WA, WB, WC, 0);
                    mac5(aA0, aB0, aA1, aB1, aC, q0, q1, cgb ? q1 : q0,
                         WA, WB, WC, 10);
                    s_ps[wid][0][adA] = hadd(aA0);
                    s_ps[wid][0][adB] = hadd(aB0);
                    s_ps[wid][1][adA] = hadd(aA1);
                    s_ps[wid][1][adB] = hadd(aB1);
                    s_ps[wid][cgb][adC] = hadd(aC);
                    __syncwarp();
                    float4 G0 = *(const float4*)&s_ps[wid][0][jc * 4];
                    float4 G1 = *(const float4*)&s_ps[wid][1][jc * 4];
                    float h0 = cellup(G0.x, G0.y, G0.z, G0.w, cst[0]);
                    float h1 = cellup(G1.x, G1.y, G1.z, G1.w, cst[1]);
                    if (lane < HID) {
                        ((float*)&s_h[2][pipe][pw][0][0])[lane] = h0;
                        ((float*)&s_h[2][pipe][pw][1][0])[lane] = h1;
                    }
                    __syncwarp();
                }
            }
        }
        // per-pipe barrier once per 2 timesteps
        asm volatile("bar.sync %0, 96;" :: "r"(barid) : "memory");
    }

    // ---- final FC on h2[T-1] (t=1023, slot 3) by the L2 warps ----
    if (role == 2) {
#pragma unroll
        for (int gb = 0; gb < GB; gb++) {
            const int b = bbase + gb;
            float hv = ((const float*)&s_h[2][pipe][3][gb][0])[jc];
            float p0 = (lane < HID) ? hv * fcw[jc]       : 0.f;
            float p1 = (lane < HID) ? hv * fcw[HID + jc] : 0.f;
#pragma unroll
            for (int off = 16; off > 0; off >>= 1) {
                p0 += __shfl_xor_sync(FULLM, p0, off);
                p1 += __shfl_xor_sync(FULLM, p1, off);
            }
            if (lane == 0) {
                out[b * 2 + 0] = p0 + fcb[0];
                out[b * 2 + 1] = p1 + fcb[1];
            }
        }
    }
}

extern "C" void kernel_launch(void* const* d_in, const int* in_sizes, int n_in,
                              void* d_out, int out_size) {
    const float* x    = (const float*)d_in[0];
    const float* wih0 = (const float*)d_in[1];
    const float* whh0 = (const float*)d_in[2];
    const float* bih0 = (const float*)d_in[3];
    const float* bhh0 = (const float*)d_in[4];
    const float* wih1 = (const float*)d_in[5];
    const float* whh1 = (const float*)d_in[6];
    const float* bih1 = (const float*)d_in[7];
    const float* bhh1 = (const float*)d_in[8];
    const float* wih2 = (const float*)d_in[9];
    const float* whh2 = (const float*)d_in[10];
    const float* bih2 = (const float*)d_in[11];
    const float* bhh2 = (const float*)d_in[12];
    const float* fcw  = (const float*)d_in[13];
    const float* fcb  = (const float*)d_in[14];
    float* out = (float*)d_out;

    // 256 blocks x 4 batches (2 pipes x GB=2); 2 blocks co-resident per SM
    lstm3_rows<<<256, NW * 32>>>(x, wih0, whh0, bih0, bhh0,
                                 wih1, whh1, bih1, bhh1,
                                 wih2, whh2, bih2, bhh2,
                                 fcw, fcb, out);
}